// round 1
// baseline (speedup 1.0000x reference)
#include <cuda_runtime.h>

// Problem constants (fixed by the reference)
#define B_  4
#define L_  8192
#define D_  1024
#define K_  7
#define HALF_ 3
#define TL_ 32          // l-positions per block
#define THREADS_ 256    // one float4 (4 channels) per thread: 256*4 = D

__global__ __launch_bounds__(THREADS_, 4)
void dwconv_mask_kernel(const float* __restrict__ x,
                        const float* __restrict__ sb,
                        const float* __restrict__ w,     // (D,1,K) -> w[d*K + k]
                        const float* __restrict__ bias,  // (D,)
                        float* __restrict__ out)
{
    __shared__ float mask_s[TL_];

    const int blk = blockIdx.x;
    const int b   = blk / (L_ / TL_);
    const int l0  = (blk % (L_ / TL_)) * TL_;
    const int t   = threadIdx.x;

    // ---- mask: count boundaries in [l-3, l+3], zero-padded; mask = 2^-count
    if (t < TL_) {
        const int l = l0 + t;
        float cnt = 0.0f;
        #pragma unroll
        for (int j = -HALF_; j <= HALF_; ++j) {
            const int p = l + j;
            if (p >= 0 && p < L_) cnt += __ldg(sb + b * L_ + p);
        }
        mask_s[t] = exp2f(-cnt);
    }

    // ---- per-thread weights for channels d0..d0+3, all 7 taps (L2-resident)
    const int d0 = t << 2;
    float4 wk[K_];
    #pragma unroll
    for (int k = 0; k < K_; ++k) {
        wk[k].x = __ldg(w + (d0 + 0) * K_ + k);
        wk[k].y = __ldg(w + (d0 + 1) * K_ + k);
        wk[k].z = __ldg(w + (d0 + 2) * K_ + k);
        wk[k].w = __ldg(w + (d0 + 3) * K_ + k);
    }
    const float4 bs = *reinterpret_cast<const float4*>(bias + d0);

    __syncthreads();

    const float* xb = x   + ((size_t)b * L_) * D_ + d0;
    float*       ob = out + ((size_t)b * L_) * D_ + d0;

    // ---- register sliding window: win[k] = x[l-6+k] (float4 over 4 channels)
    float4 win[K_];
    #pragma unroll
    for (int k = 0; k < K_; ++k) {
        const int l = l0 - (K_ - 1) + k;
        if (l >= 0)
            win[k] = *reinterpret_cast<const float4*>(xb + (size_t)l * D_);
        else
            win[k] = make_float4(0.f, 0.f, 0.f, 0.f);
    }

    #pragma unroll
    for (int i = 0; i < TL_; ++i) {
        float4 acc = bs;
        #pragma unroll
        for (int k = 0; k < K_; ++k) {
            acc.x = fmaf(win[k].x, wk[k].x, acc.x);
            acc.y = fmaf(win[k].y, wk[k].y, acc.y);
            acc.z = fmaf(win[k].z, wk[k].z, acc.z);
            acc.w = fmaf(win[k].w, wk[k].w, acc.w);
        }
        const float m = mask_s[i];
        acc.x *= m; acc.y *= m; acc.z *= m; acc.w *= m;
        *reinterpret_cast<float4*>(ob + (size_t)(l0 + i) * D_) = acc;

        if (i < TL_ - 1) {
            #pragma unroll
            for (int k = 0; k < K_ - 1; ++k) win[k] = win[k + 1];
            win[K_ - 1] = *reinterpret_cast<const float4*>(
                xb + (size_t)(l0 + i + 1) * D_);
        }
    }
}

extern "C" void kernel_launch(void* const* d_in, const int* in_sizes, int n_in,
                              void* d_out, int out_size)
{
    const float* x    = (const float*)d_in[0];  // (B,L,D)
    const float* sb   = (const float*)d_in[1];  // (B,L)
    const float* w    = (const float*)d_in[2];  // (D,1,K)
    const float* bias = (const float*)d_in[3];  // (D,)
    float* out        = (float*)d_out;          // (B,L,D)

    const int blocks = B_ * (L_ / TL_);         // 1024
    dwconv_mask_kernel<<<blocks, THREADS_>>>(x, sb, w, bias, out);
}

// round 2
// speedup vs baseline: 1.4655x; 1.4655x over previous
#include <cuda_runtime.h>

// Problem constants (fixed by the reference)
#define B_  4
#define L_  8192
#define D_  1024
#define K_  7
#define HALF_ 3
#define TL_ 32          // l-positions per block
#define G_  4           // outputs per group (prefetch batch size)
#define THREADS_ 256    // one float4 (4 channels) per thread: 256*4 = D

__global__ __launch_bounds__(THREADS_)
void dwconv_mask_kernel(const float* __restrict__ x,
                        const float* __restrict__ sb,
                        const float* __restrict__ w,     // (D,1,K) -> w[d*K + k]
                        const float* __restrict__ bias,  // (D,)
                        float* __restrict__ out)
{
    __shared__ float mask_s[TL_];

    const int blk = blockIdx.x;
    const int b   = blk / (L_ / TL_);
    const int l0  = (blk % (L_ / TL_)) * TL_;
    const int t   = threadIdx.x;

    // ---- mask: count boundaries in [l-3, l+3], zero-padded; mask = 2^-count
    if (t < TL_) {
        const int l = l0 + t;
        float cnt = 0.0f;
        #pragma unroll
        for (int j = -HALF_; j <= HALF_; ++j) {
            const int p = l + j;
            if (p >= 0 && p < L_) cnt += __ldg(sb + b * L_ + p);
        }
        mask_s[t] = exp2f(-cnt);
    }

    // ---- per-thread weights for channels d0..d0+3, all 7 taps (L2-resident)
    const int d0 = t << 2;
    float4 wk[K_];
    #pragma unroll
    for (int k = 0; k < K_; ++k) {
        wk[k].x = __ldg(w + (d0 + 0) * K_ + k);
        wk[k].y = __ldg(w + (d0 + 1) * K_ + k);
        wk[k].z = __ldg(w + (d0 + 2) * K_ + k);
        wk[k].w = __ldg(w + (d0 + 3) * K_ + k);
    }
    const float4 bs = *reinterpret_cast<const float4*>(bias + d0);

    __syncthreads();

    const float* xb = x   + ((size_t)b * L_) * D_ + d0;
    float*       ob = out + ((size_t)b * L_) * D_ + d0;

    // ---- register window: win[k] = x[row l0-6+k], k=0..6  (rows l0-6..l0)
    float4 win[K_];
    #pragma unroll
    for (int k = 0; k < K_; ++k) {
        const int l = l0 - (K_ - 1) + k;
        if (l >= 0)
            win[k] = *reinterpret_cast<const float4*>(xb + (size_t)l * D_);
        else
            win[k] = make_float4(0.f, 0.f, 0.f, 0.f);
    }

    // ---- groups of G_ outputs; 4 independent prefetch loads per group
    #pragma unroll
    for (int g = 0; g < TL_ / G_; ++g) {
        const int base = l0 + g * G_;   // window currently holds rows base-6..base

        // batched prefetch: rows base+1 .. base+4 (4 independent LDG.128)
        float4 nxt[G_];
        #pragma unroll
        for (int j = 0; j < G_; ++j) {
            // nxt[3] (row base+4) only feeds the NEXT group's window;
            // skip in the final group (row may be == L_)
            if (j < G_ - 1 || g < TL_ / G_ - 1)
                nxt[j] = *reinterpret_cast<const float4*>(
                    xb + (size_t)(base + 1 + j) * D_);
            else
                nxt[j] = make_float4(0.f, 0.f, 0.f, 0.f);
        }

        // compute 4 outputs: output base+i uses rows base+i-6 .. base+i
        #pragma unroll
        for (int i = 0; i < G_; ++i) {
            float4 acc = bs;
            #pragma unroll
            for (int k = 0; k < K_; ++k) {
                // tap k reads row (base+i-6+k): win[i+k] if i+k<7 else nxt[i+k-7]
                const float4 v = (i + k < K_) ? win[i + k] : nxt[i + k - K_];
                acc.x = fmaf(v.x, wk[k].x, acc.x);
                acc.y = fmaf(v.y, wk[k].y, acc.y);
                acc.z = fmaf(v.z, wk[k].z, acc.z);
                acc.w = fmaf(v.w, wk[k].w, acc.w);
            }
            const float m = mask_s[g * G_ + i];
            acc.x *= m; acc.y *= m; acc.z *= m; acc.w *= m;
            *reinterpret_cast<float4*>(ob + (size_t)(base + i) * D_) = acc;
        }

        // rotate window by G_: new window = rows base-2 .. base+4
        #pragma unroll
        for (int k = 0; k < K_ - G_; ++k) win[k] = win[k + G_];
        #pragma unroll
        for (int j = 0; j < G_; ++j)      win[K_ - G_ + j] = nxt[j];
    }
}

extern "C" void kernel_launch(void* const* d_in, const int* in_sizes, int n_in,
                              void* d_out, int out_size)
{
    const float* x    = (const float*)d_in[0];  // (B,L,D)
    const float* sb   = (const float*)d_in[1];  // (B,L)
    const float* w    = (const float*)d_in[2];  // (D,1,K)
    const float* bias = (const float*)d_in[3];  // (D,)
    float* out        = (float*)d_out;          // (B,L,D)

    const int blocks = B_ * (L_ / TL_);         // 1024
    dwconv_mask_kernel<<<blocks, THREADS_>>>(x, sb, w, bias, out);
}

// round 3
// speedup vs baseline: 1.5164x; 1.0348x over previous
#include <cuda_runtime.h>

// Problem constants (fixed by the reference)
#define B_  4
#define L_  8192
#define D_  1024
#define K_  7
#define HALF_ 3
#define TL_ 32          // l-positions per block
#define G_  8           // outputs per group (prefetch batch size)
#define THREADS_ 256    // one float4 (4 channels) per thread: 256*4 = D

__global__ __launch_bounds__(THREADS_)
void dwconv_mask_kernel(const float* __restrict__ x,
                        const float* __restrict__ sb,
                        const float* __restrict__ w,     // (D,1,K) -> w[d*K + k]
                        const float* __restrict__ bias,  // (D,)
                        float* __restrict__ out)
{
    __shared__ float mask_s[TL_];

    const int blk = blockIdx.x;
    const int b   = blk / (L_ / TL_);
    const int l0  = (blk % (L_ / TL_)) * TL_;
    const int t   = threadIdx.x;

    // ---- mask: count boundaries in [l-3, l+3], zero-padded; mask = 2^-count
    if (t < TL_) {
        const int l = l0 + t;
        float cnt = 0.0f;
        #pragma unroll
        for (int j = -HALF_; j <= HALF_; ++j) {
            const int p = l + j;
            if (p >= 0 && p < L_) cnt += __ldg(sb + b * L_ + p);
        }
        mask_s[t] = exp2f(-cnt);
    }

    // ---- per-thread weights for channels d0..d0+3, all 7 taps (L2-resident)
    const int d0 = t << 2;
    float4 wk[K_];
    #pragma unroll
    for (int k = 0; k < K_; ++k) {
        wk[k].x = __ldg(w + (d0 + 0) * K_ + k);
        wk[k].y = __ldg(w + (d0 + 1) * K_ + k);
        wk[k].z = __ldg(w + (d0 + 2) * K_ + k);
        wk[k].w = __ldg(w + (d0 + 3) * K_ + k);
    }
    const float4 bs = *reinterpret_cast<const float4*>(bias + d0);

    __syncthreads();

    const float* xb = x   + ((size_t)b * L_) * D_ + d0;
    float*       ob = out + ((size_t)b * L_) * D_ + d0;

    // ---- register window: win[k] = x[row l0-6+k], k=0..6  (rows l0-6..l0)
    float4 win[K_];
    #pragma unroll
    for (int k = 0; k < K_; ++k) {
        const int l = l0 - (K_ - 1) + k;
        if (l >= 0)
            win[k] = *reinterpret_cast<const float4*>(xb + (size_t)l * D_);
        else
            win[k] = make_float4(0.f, 0.f, 0.f, 0.f);
    }

    // ---- groups of G_ outputs; G_ independent prefetch loads per group
    #pragma unroll
    for (int g = 0; g < TL_ / G_; ++g) {
        const int base = l0 + g * G_;   // window holds rows base-6..base

        // batched prefetch: rows base+1 .. base+G_ (independent LDG.128)
        float4 nxt[G_];
        #pragma unroll
        for (int j = 0; j < G_; ++j) {
            // nxt[G_-1] (row base+G_) only feeds the NEXT group's window;
            // skip in the final group (row may be == L_ for the last tile)
            if (j < G_ - 1 || g < TL_ / G_ - 1)
                nxt[j] = *reinterpret_cast<const float4*>(
                    xb + (size_t)(base + 1 + j) * D_);
            else
                nxt[j] = make_float4(0.f, 0.f, 0.f, 0.f);
        }

        // compute G_ outputs: output base+i uses rows base+i-6 .. base+i
        #pragma unroll
        for (int i = 0; i < G_; ++i) {
            float4 acc = bs;
            #pragma unroll
            for (int k = 0; k < K_; ++k) {
                // tap k reads row (base+i-6+k): win[i+k] if i+k<7 else nxt[i+k-7]
                const float4 v = (i + k < K_) ? win[i + k] : nxt[i + k - K_];
                acc.x = fmaf(v.x, wk[k].x, acc.x);
                acc.y = fmaf(v.y, wk[k].y, acc.y);
                acc.z = fmaf(v.z, wk[k].z, acc.z);
                acc.w = fmaf(v.w, wk[k].w, acc.w);
            }
            const float m = mask_s[g * G_ + i];
            acc.x *= m; acc.y *= m; acc.z *= m; acc.w *= m;
            // streaming store: out is write-once; don't pollute L2 (keep halo)
            __stcs(reinterpret_cast<float4*>(ob + (size_t)(base + i) * D_), acc);
        }

        // rotate window by G_: new window = rows base+G_-6 .. base+G_
        #pragma unroll
        for (int k = 0; k < K_ - 1; ++k) {
            // win[k] <- row (base+G_-6+k). Since G_=8 > 6, all new window
            // rows come from nxt: row base+G_-6+k = nxt[G_-7+k]
            win[k] = nxt[G_ - K_ + k];
        }
        win[K_ - 1] = nxt[G_ - 1];
    }
}

extern "C" void kernel_launch(void* const* d_in, const int* in_sizes, int n_in,
                              void* d_out, int out_size)
{
    const float* x    = (const float*)d_in[0];  // (B,L,D)
    const float* sb   = (const float*)d_in[1];  // (B,L)
    const float* w    = (const float*)d_in[2];  // (D,1,K)
    const float* bias = (const float*)d_in[3];  // (D,)
    float* out        = (float*)d_out;          // (B,L,D)

    const int blocks = B_ * (L_ / TL_);         // 1024
    dwconv_mask_kernel<<<blocks, THREADS_>>>(x, sb, w, bias, out);
}

// round 4
// speedup vs baseline: 1.5202x; 1.0025x over previous
#include <cuda_runtime.h>

// Problem constants (fixed by the reference)
#define B_  4
#define L_  8192
#define D_  1024
#define K_  7
#define HALF_ 3
#define G_  8            // rows per group = prefetch batch depth
#define THREADS_ 256     // one float4 (4 channels) per thread: 256*4 = D
#define NBLK_PER_B_ 152  // strips per batch; grid = 4*152 = 608
#define MAXROWS_ 64      // >= ceil(ceil(8192/152)/8)*8 = 56

__global__ __launch_bounds__(THREADS_, 2)
void dwconv_mask_kernel(const float* __restrict__ x,
                        const float* __restrict__ sb,
                        const float* __restrict__ w,     // (D,1,K) -> w[d*K + k]
                        const float* __restrict__ bias,  // (D,)
                        float* __restrict__ out)
{
    __shared__ float mask_s[MAXROWS_];

    const int b  = blockIdx.x / NBLK_PER_B_;
    const int j  = blockIdx.x % NBLK_PER_B_;
    const int r0 = (j * L_) / NBLK_PER_B_;        // strip start row (within batch)
    const int r1 = ((j + 1) * L_) / NBLK_PER_B_;  // strip end (exclusive)
    const int t  = threadIdx.x;

    // ---- masks for the whole strip: count boundaries in [l-3,l+3], mask=2^-cnt
    if (t < MAXROWS_) {
        const int l = r0 + t;
        float m = 0.0f;
        if (l < L_) {
            float cnt = 0.0f;
            #pragma unroll
            for (int q = -HALF_; q <= HALF_; ++q) {
                const int p = l + q;
                if (p >= 0 && p < L_) cnt += __ldg(sb + b * L_ + p);
            }
            m = exp2f(-cnt);
        }
        mask_s[t] = m;
    }

    // ---- per-thread weights for channels d0..d0+3 (L2-resident)
    const int d0 = t << 2;
    float4 wk[K_];
    #pragma unroll
    for (int k = 0; k < K_; ++k) {
        wk[k].x = __ldg(w + (d0 + 0) * K_ + k);
        wk[k].y = __ldg(w + (d0 + 1) * K_ + k);
        wk[k].z = __ldg(w + (d0 + 2) * K_ + k);
        wk[k].w = __ldg(w + (d0 + 3) * K_ + k);
    }
    const float4 bs = *reinterpret_cast<const float4*>(bias + d0);

    __syncthreads();

    const float* xb = x   + ((size_t)b * L_) * D_ + d0;
    float*       ob = out + ((size_t)b * L_) * D_ + d0;

    // ---- register window: win[k] = row r0-6+k (rows r0-6 .. r0)
    float4 win[K_];
    #pragma unroll
    for (int k = 0; k < K_; ++k) {
        const int l = r0 - (K_ - 1) + k;
        if (l >= 0)
            win[k] = *reinterpret_cast<const float4*>(xb + (size_t)l * D_);
        else
            win[k] = make_float4(0.f, 0.f, 0.f, 0.f);
    }

    const int nrows   = r1 - r0;
    const int ngroups = (nrows + G_ - 1) / G_;

    for (int g = 0; g < ngroups; ++g) {
        const int base = r0 + g * G_;   // window holds rows base-6 .. base

        // batched prefetch: rows base+1 .. base+8 (8 independent LDG.128)
        float4 nxt[G_];
        #pragma unroll
        for (int p = 0; p < G_; ++p) {
            const int l = base + 1 + p;
            if (l < L_)
                nxt[p] = *reinterpret_cast<const float4*>(xb + (size_t)l * D_);
            else
                nxt[p] = make_float4(0.f, 0.f, 0.f, 0.f);
        }

        // compute 8 outputs: output base+i uses rows base+i-6 .. base+i
        #pragma unroll
        for (int i = 0; i < G_; ++i) {
            float4 acc = bs;
            #pragma unroll
            for (int k = 0; k < K_; ++k) {
                const float4 v = (i + k < K_) ? win[i + k] : nxt[i + k - K_];
                acc.x = fmaf(v.x, wk[k].x, acc.x);
                acc.y = fmaf(v.y, wk[k].y, acc.y);
                acc.z = fmaf(v.z, wk[k].z, acc.z);
                acc.w = fmaf(v.w, wk[k].w, acc.w);
            }
            const float m = mask_s[g * G_ + i];
            acc.x *= m; acc.y *= m; acc.z *= m; acc.w *= m;
            const int l = base + i;
            if (l < r1)   // strip-exclusive store (avoid cross-block duplicates)
                __stcs(reinterpret_cast<float4*>(ob + (size_t)l * D_), acc);
        }

        // rotate: new window = rows base+2 .. base+8 = nxt[1..7]
        #pragma unroll
        for (int k = 0; k < K_; ++k) win[k] = nxt[k + 1];
    }
}

extern "C" void kernel_launch(void* const* d_in, const int* in_sizes, int n_in,
                              void* d_out, int out_size)
{
    const float* x    = (const float*)d_in[0];  // (B,L,D)
    const float* sb   = (const float*)d_in[1];  // (B,L)
    const float* w    = (const float*)d_in[2];  // (D,1,K)
    const float* bias = (const float*)d_in[3];  // (D,)
    float* out        = (float*)d_out;          // (B,L,D)

    dwconv_mask_kernel<<<B_ * NBLK_PER_B_, THREADS_>>>(x, sb, w, bias, out);
}

// round 5
// speedup vs baseline: 1.5771x; 1.0374x over previous
#include <cuda_runtime.h>

// Problem constants (fixed by the reference)
#define B_       4
#define L_       8192
#define D_       1024
#define K_       7
#define HALF_    3
#define THREADS_ 256      // one float4 (4 channels) per thread: 256*4 = D
#define ROWS_    54       // output rows per strip
#define STRIPS_  152      // ceil(8192/54); grid = 4*152 = 608
#define NSTREAM_ 60       // rows consumed per strip = ROWS_ + K_ - 1
#define PIPE_    10       // smem ring depth (rows); NSTREAM_ % PIPE_ == 0
#define AHEAD_   8        // prefetch distance (< PIPE_ for WAR gap)
#define ROWBYTES_ (THREADS_ * 16)   // 4096 B per ring stage

__global__ __launch_bounds__(THREADS_, 3)
void dwconv_pipe_kernel(const float* __restrict__ x,
                        const float* __restrict__ sb,
                        const float* __restrict__ w,     // (D,1,K) -> w[d*K + k]
                        const float* __restrict__ bias,  // (D,)
                        float* __restrict__ out)
{
    __shared__ __align__(16) float4 ring[PIPE_][THREADS_];
    __shared__ float mask_s[ROWS_];

    const int b  = blockIdx.x / STRIPS_;
    const int j  = blockIdx.x % STRIPS_;
    const int r0 = j * ROWS_;
    const int r1 = min(r0 + ROWS_, L_);
    const int t  = threadIdx.x;

    // ---- masks for strip rows: count boundaries in [l-3,l+3], mask = 2^-cnt
    if (t < ROWS_) {
        const int l = r0 + t;
        float m = 0.0f;
        if (l < L_) {
            float cnt = 0.0f;
            #pragma unroll
            for (int q = -HALF_; q <= HALF_; ++q) {
                const int p = l + q;
                if (p >= 0 && p < L_) cnt += __ldg(sb + b * L_ + p);
            }
            m = exp2f(-cnt);
        }
        mask_s[t] = m;
    }

    // ---- per-thread weights for channels d0..d0+3 (L2-resident)
    const int d0 = t << 2;
    float4 wk[K_];
    #pragma unroll
    for (int k = 0; k < K_; ++k) {
        wk[k].x = __ldg(w + (d0 + 0) * K_ + k);
        wk[k].y = __ldg(w + (d0 + 1) * K_ + k);
        wk[k].z = __ldg(w + (d0 + 2) * K_ + k);
        wk[k].w = __ldg(w + (d0 + 3) * K_ + k);
    }
    const float4 bs = *reinterpret_cast<const float4*>(bias + d0);

    const float* xb = x   + ((size_t)b * L_) * D_ + d0;
    float*       ob = out + ((size_t)b * L_) * D_ + d0;

    const int lr_first = r0 - (K_ - 1);

    const unsigned ring_base =
        (unsigned)__cvta_generic_to_shared(&ring[0][t]);

    // ---- prologue: issue AHEAD_ rows (stages 0..AHEAD_-1), one group each
    #pragma unroll
    for (int s = 0; s < AHEAD_; ++s) {
        const int lr = lr_first + s;
        const int lc = lr < 0 ? 0 : lr;          // clamp; garbage zeroed at use
        const float* src = xb + (size_t)lc * D_;
        asm volatile("cp.async.cg.shared.global [%0], [%1], 16;"
                     :: "r"(ring_base + s * ROWBYTES_), "l"(src));
        asm volatile("cp.async.commit_group;");
    }

    __syncthreads();   // mask_s ready (does not affect per-thread cp.async)

    float4 win[K_];    // filled during first K_-1 iterations (guarded compute)
    #pragma unroll
    for (int k = 0; k < K_; ++k) win[k] = make_float4(0.f, 0.f, 0.f, 0.f);

    #pragma unroll 1
    for (int io = 0; io < NSTREAM_ / PIPE_; ++io) {
        #pragma unroll
        for (int ii = 0; ii < PIPE_; ++ii) {
            const int i  = io * PIPE_ + ii;
            const int lr = lr_first + i;

            // issue prefetch for row i+AHEAD_ (stage (ii+AHEAD_)%PIPE_, static)
            {
                const int ip = i + AHEAD_;
                if (ip < NSTREAM_) {
                    int lrp = lr_first + ip;
                    int lc  = lrp < 0 ? 0 : (lrp >= L_ ? L_ - 1 : lrp);
                    const float* src = xb + (size_t)lc * D_;
                    asm volatile("cp.async.cg.shared.global [%0], [%1], 16;"
                                 :: "r"(ring_base +
                                        ((ii + AHEAD_) % PIPE_) * ROWBYTES_),
                                    "l"(src));
                }
                asm volatile("cp.async.commit_group;");
            }
            // row i complete when at most AHEAD_ groups pending
            asm volatile("cp.async.wait_group %0;" :: "n"(AHEAD_) : "memory");

            // consume row lr (thread reads back only its own 16 B)
            float4 v = ring[ii][t];
            if (lr < 0) v = make_float4(0.f, 0.f, 0.f, 0.f);

            // slide window: win = rows lr-6 .. lr
            #pragma unroll
            for (int k = 0; k < K_ - 1; ++k) win[k] = win[k + 1];
            win[K_ - 1] = v;

            if (lr >= r0 && lr < r1) {
                float4 acc = bs;
                #pragma unroll
                for (int k = 0; k < K_; ++k) {
                    acc.x = fmaf(win[k].x, wk[k].x, acc.x);
                    acc.y = fmaf(win[k].y, wk[k].y, acc.y);
                    acc.z = fmaf(win[k].z, wk[k].z, acc.z);
                    acc.w = fmaf(win[k].w, wk[k].w, acc.w);
                }
                const float m = mask_s[lr - r0];
                acc.x *= m; acc.y *= m; acc.z *= m; acc.w *= m;
                __stcs(reinterpret_cast<float4*>(ob + (size_t)lr * D_), acc);
            }
        }
    }
}

extern "C" void kernel_launch(void* const* d_in, const int* in_sizes, int n_in,
                              void* d_out, int out_size)
{
    const float* x    = (const float*)d_in[0];  // (B,L,D)
    const float* sb   = (const float*)d_in[1];  // (B,L)
    const float* w    = (const float*)d_in[2];  // (D,1,K)
    const float* bias = (const float*)d_in[3];  // (D,)
    float* out        = (float*)d_out;          // (B,L,D)

    dwconv_pipe_kernel<<<B_ * STRIPS_, THREADS_>>>(x, sb, w, bias, out);
}